// round 7
// baseline (speedup 1.0000x reference)
#include <cuda_runtime.h>
#include <float.h>
#include <math.h>

// Problem constants (shapes fixed by the dataset)
#define DIM       256
#define MAXB      128
#define TOPK      32
#define CAND_CAP  65536

#define INV_TAU   10.0f     // 1 / 0.1
#define PEN_COEF  0.25f     // BETA / (2*SIGMA^2) = 0.5 / 2
#define SIM_BOUND 10.0f     // max |q.K| / tau  (q, K unit-norm)

#define QG 32               // queries per logits block
#define CG 64               // candidates per logits chunk
#define PRE_BLOCKS 148      // <= SM count: all resident -> spin barrier is safe
#define P_PARTS 8           // selection parts per query
#define EQCAP 2048          // per-part element capacity (fast path)

// ---------------- scratch (device globals; no allocation allowed) ----------
__device__ unsigned int g_ctr;                       // monotonic epoch counter
__device__ int          g_count;
__device__ int          g_qdone[MAXB];
__device__ float        g_minblk[PRE_BLOCKS][32];
__device__ int          g_cidx[CAND_CAP];
__device__ float        g_cpen[CAND_CAP];
__device__ float        g_qn[MAXB * DIM];
__device__ float        g_logits[(size_t)MAXB * CAND_CAP];           // 32 MB
__device__ unsigned long long g_pk[MAXB][P_PARTS * TOPK];            // staging

// order-preserving float <-> uint (descending float == descending uint)
__device__ __forceinline__ unsigned int f2u_ord(float f) {
    unsigned int u = __float_as_uint(f);
    return (u & 0x80000000u) ? ~u : (u | 0x80000000u);
}
__device__ __forceinline__ float u2f_ord(unsigned int u) {
    return (u & 0x80000000u) ? __uint_as_float(u & 0x7FFFFFFFu)
                             : __uint_as_float(~u);
}
// 64-bit selection key: value (ordered) high, ~index low. Distinct keys;
// bigger == better; lower index wins ties (== jax top_k order).
__device__ __forceinline__ unsigned long long mk_key(float v, int m) {
    return ((unsigned long long)f2u_ord(v) << 32) |
           (unsigned int)(~(unsigned int)m);
}

// ---------------------------------------------------------------------------
// Kernel 1 (fused): reset + query L2-norm + per-residue penalty minima +
// monotonic grid barrier + threshold + candidate compaction. Grid = 148.
// Threshold soundness: rows partitioned into 32 disjoint groups by (n mod 32);
// max over the 32 per-group minima >= 32nd-smallest penalty, so
// thresh = bound + 2*SIM_BOUND + margin never drops a true top-32 row.
// The barrier uses epoch arithmetic (each launch adds exactly nb tickets), so
// no counter reset is needed across CUDA-graph replays.
// ---------------------------------------------------------------------------
__global__ void __launch_bounds__(256) k_pre(const float* __restrict__ times,
                                             const float* __restrict__ qtime,
                                             const float* __restrict__ query,
                                             int N, int B) {
    __shared__ float s[256];
    __shared__ float sth;
    int tid = threadIdx.x, bid = blockIdx.x;
    int nb = gridDim.x;

    // --- per-launch resets (visible after barrier) ---
    if (bid == 0) {
        if (tid == 0) g_count = 0;
        if (tid < MAXB) g_qdone[tid] = 0;
    }

    // --- query L2 normalization (matches F.normalize, eps=1e-12) ---
    if (bid < B) {
        float v = query[bid * DIM + tid];
        s[tid] = v * v;
        __syncthreads();
        #pragma unroll
        for (int st = 128; st > 0; st >>= 1) {
            if (tid < st) s[tid] += s[tid + st];
            __syncthreads();
        }
        float nrm = fmaxf(sqrtf(s[0]), 1e-12f);
        __syncthreads();
        g_qn[bid * DIM + tid] = v / nrm;
    }

    // --- per-residue-group penalty minima (residue fixed: stride % 32 == 0) ---
    float qt = qtime[0];
    float lmin = FLT_MAX;
    int stride = nb * 256;
    for (int n = bid * 256 + tid; n < N; n += stride) {
        float dt = qt - times[n];
        lmin = fminf(lmin, PEN_COEF * dt * dt);
    }
    s[tid] = lmin;
    __syncthreads();
    if (tid < 32) {
        float m = s[tid];
        #pragma unroll
        for (int w = 1; w < 8; w++) m = fminf(m, s[w * 32 + tid]);
        g_minblk[bid][tid] = m;              // plain store, no init needed
    }
    __threadfence();
    __syncthreads();

    // --- monotonic grid barrier ---
    if (tid == 0) {
        unsigned int ticket = atomicAdd(&g_ctr, 1u);
        unsigned int target = (ticket / nb + 1u) * nb;
        while (atomicAdd(&g_ctr, 0u) < target) __nanosleep(32);
        __threadfence();
    }
    __syncthreads();

    // --- threshold: min over blocks per residue, then max over residues ---
    {
        int r = tid & 31, w = tid >> 5;
        float m = FLT_MAX;
        for (int i = w; i < nb; i += 8) m = fminf(m, g_minblk[i][r]);
        s[tid] = m;
        __syncthreads();
        if (tid < 32) {
            float mm = s[tid];
            #pragma unroll
            for (int ww = 1; ww < 8; ww++) mm = fminf(mm, s[ww * 32 + tid]);
            s[tid] = mm;
        }
        __syncthreads();
        if (tid == 0) {
            float mx = -FLT_MAX;
            #pragma unroll
            for (int g = 0; g < 32; g++) mx = fmaxf(mx, s[g]);
            sth = mx + 2.0f * SIM_BOUND + 4.0f;   // sound bound + fp margin
        }
        __syncthreads();
    }
    float thresh = sth;

    // --- compact candidate rows ---
    for (int n = bid * 256 + tid; n < N; n += stride) {
        float dt = qt - times[n];
        float p = PEN_COEF * dt * dt;
        if (p <= thresh) {
            int pos = atomicAdd(&g_count, 1);
            if (pos < CAND_CAP) { g_cidx[pos] = n; g_cpen[pos] = p; }
        }
    }
}

// ---------------------------------------------------------------------------
// Kernel 2: exact fp32 logits, register-tiled (R5-proven version).
// Block tile QG=32 x CG=64, 128 threads, 4x4 register tile, 96 KB SMEM,
// 2 blocks/SM. Inner d-step: 2x LDS.128 + 16 FMA.
// ---------------------------------------------------------------------------
extern __shared__ float s_dyn[];   // qs[DIM*QG] then kv[DIM*CG]

__global__ void __launch_bounds__(128, 2)
k_logits(const float* __restrict__ Kbank, int B) {
    float* qs = s_dyn;             // [d*QG + q]
    float* kv = s_dyn + DIM * QG;  // [d*CG + c]
    __shared__ float spen[CG];

    int tid = threadIdx.x;
    int grp = blockIdx.y;
    int cnt = min(g_count, CAND_CAP);
    if (cnt <= 0) return;

    const float4* qn4 = (const float4*)g_qn;
    const float4* K4  = (const float4*)Kbank;

    // ---- load 32 queries transposed ----
    {
        int q = tid & 31, d4b = tid >> 5;
        int b = grp * QG + q;
        #pragma unroll
        for (int i = 0; i < 16; i++) {
            int d4 = d4b + 4 * i;
            float4 v = (b < B) ? qn4[(size_t)b * (DIM / 4) + d4]
                               : make_float4(0.f, 0.f, 0.f, 0.f);
            qs[(d4 * 4 + 0) * QG + q] = v.x;
            qs[(d4 * 4 + 1) * QG + q] = v.y;
            qs[(d4 * 4 + 2) * QG + q] = v.z;
            qs[(d4 * 4 + 3) * QG + q] = v.w;
        }
    }

    int cq = tid & 15, qq = tid >> 4;
    int c0 = cq * 4, q0 = qq * 4;

    for (int m0 = blockIdx.x * CG; m0 < cnt; m0 += gridDim.x * CG) {
        __syncthreads();

        // ---- load 64 candidate K rows transposed ----
        {
            int c = tid & 63, d4b = tid >> 6;
            int row = g_cidx[min(m0 + c, cnt - 1)];
            #pragma unroll
            for (int i = 0; i < 32; i++) {
                int d4 = d4b + 2 * i;
                float4 v = K4[(size_t)row * (DIM / 4) + d4];
                kv[(d4 * 4 + 0) * CG + c] = v.x;
                kv[(d4 * 4 + 1) * CG + c] = v.y;
                kv[(d4 * 4 + 2) * CG + c] = v.z;
                kv[(d4 * 4 + 3) * CG + c] = v.w;
            }
        }
        if (tid < CG) spen[tid] = g_cpen[min(m0 + tid, cnt - 1)];
        __syncthreads();

        float acc[16];
        #pragma unroll
        for (int i = 0; i < 16; i++) acc[i] = 0.0f;

        #pragma unroll 4
        for (int d = 0; d < DIM; d++) {
            float4 kf = *(const float4*)&kv[d * CG + c0];
            float4 qf = *(const float4*)&qs[d * QG + q0];
            acc[0]  += qf.x * kf.x;  acc[1]  += qf.x * kf.y;
            acc[2]  += qf.x * kf.z;  acc[3]  += qf.x * kf.w;
            acc[4]  += qf.y * kf.x;  acc[5]  += qf.y * kf.y;
            acc[6]  += qf.y * kf.z;  acc[7]  += qf.y * kf.w;
            acc[8]  += qf.z * kf.x;  acc[9]  += qf.z * kf.y;
            acc[10] += qf.z * kf.z;  acc[11] += qf.z * kf.w;
            acc[12] += qf.w * kf.x;  acc[13] += qf.w * kf.y;
            acc[14] += qf.w * kf.z;  acc[15] += qf.w * kf.w;
        }

        float p0 = spen[c0 + 0], p1 = spen[c0 + 1];
        float p2 = spen[c0 + 2], p3 = spen[c0 + 3];
        bool full = (m0 + c0 + 3) < cnt;
        #pragma unroll
        for (int qj = 0; qj < 4; qj++) {
            int b = grp * QG + q0 + qj;
            if (b >= B) break;
            float* dst = g_logits + (size_t)b * CAND_CAP + m0 + c0;
            float4 v;
            v.x = acc[qj * 4 + 0] * INV_TAU - p0;
            v.y = acc[qj * 4 + 1] * INV_TAU - p1;
            v.z = acc[qj * 4 + 2] * INV_TAU - p2;
            v.w = acc[qj * 4 + 3] * INV_TAU - p3;
            if (full) {
                *(float4*)dst = v;
            } else {
                float vv[4] = {v.x, v.y, v.z, v.w};
                for (int cj = 0; cj < 4; cj++)
                    if (m0 + c0 + cj < cnt) dst[cj] = vv[cj];
            }
        }
    }
}

// ---------------------------------------------------------------------------
// Warp-0 register suffix-scan over a 256-bin histogram; returns the unique
// bin t with sfx[t] >= K and sfx[t+1] < K via *out. 8 bins/lane + 5 shfls.
// ---------------------------------------------------------------------------
__device__ __forceinline__ void warp_cutoff(const unsigned int* h, int K,
                                            int* out, int lane) {
    unsigned int loc[8];
    int b8 = lane * 8;
    #pragma unroll
    for (int k = 0; k < 8; k++) loc[k] = h[b8 + k];
    #pragma unroll
    for (int k = 6; k >= 0; k--) loc[k] += loc[k + 1];      // local suffix
    unsigned int total = loc[0];
    unsigned int val = total;
    #pragma unroll
    for (int off = 1; off < 32; off <<= 1) {
        unsigned int o = __shfl_down_sync(0xFFFFFFFFu, val, off);
        if (lane + off < 32) val += o;
    }
    unsigned int excl = val - total;                        // suffix of lanes > lane
    #pragma unroll
    for (int k = 0; k < 8; k++) {
        unsigned int sfx = loc[k] + excl;
        unsigned int abv = (k < 7) ? (loc[k + 1] + excl) : excl;
        if (sfx >= (unsigned)K && abv < (unsigned)K) *out = b8 + k;
    }
}

// ---------------------------------------------------------------------------
// Kernel 3: per (query, part) EXACT top-32 via radix select on 64-bit keys
// staged in SMEM, then the LAST part block per query merges all 256 staged
// keys by rank, softmaxes, and gathers V. Grid (P_PARTS, B), 256 threads.
// ---------------------------------------------------------------------------
__global__ void __launch_bounds__(256) k_sel(const float* __restrict__ Vbank,
                                             float* __restrict__ out, int B) {
    __shared__ unsigned long long keys[EQCAP];
    __shared__ unsigned short eqi[2][EQCAP];
    __shared__ unsigned int h0[256];
    __shared__ unsigned long long wink[TOPK];
    __shared__ unsigned long long red[8];
    __shared__ int s_nwin, s_neq[2], s_b, s_last;
    __shared__ float sv[TOPK];
    __shared__ int   si[TOPK];

    int p = blockIdx.x, b = blockIdx.y;
    int tid = threadIdx.x, lane = tid & 31, warp = tid >> 5;
    int cnt = min(g_count, CAND_CAP);
    float* grow = g_logits + (size_t)b * CAND_CAP;

    int base = (int)(((long long)cnt * p) / P_PARTS);
    int end  = (int)(((long long)cnt * (p + 1)) / P_PARTS);
    int np = end - base;
    int selk = min(TOPK, np);

    if (tid == 0) { s_nwin = 0; s_neq[0] = 0; s_neq[1] = 0; }
    h0[tid] = 0u;
    __syncthreads();

    if (np > 0 && np <= EQCAP) {
        // ---- single gmem pass: stage keys in SMEM + histogram byte 7 ----
        for (int i = tid; i < np; i += 256) {
            unsigned long long key = mk_key(grow[base + i], base + i);
            keys[i] = key;
            unsigned int bin = (unsigned int)(key >> 56);
            unsigned int am = __activemask();
            unsigned int mk = __match_any_sync(am, bin);
            if (lane == __ffs(mk) - 1) atomicAdd(&h0[bin], __popc(mk));
        }
        __syncthreads();
        if (warp == 0) warp_cutoff(h0, selk, &s_b, lane);
        __syncthreads();
        int bs = s_b;
        for (int i = tid; i < np; i += 256) {
            int byt = (int)(keys[i] >> 56);
            if (byt > bs) {
                int q = atomicAdd(&s_nwin, 1);
                wink[q] = keys[i];
            } else if (byt == bs) {
                int q = atomicAdd(&s_neq[0], 1);
                eqi[0][q] = (unsigned short)i;
            }
        }
        __syncthreads();

        // ---- levels 1..7 over the shrinking equals list ----
        int cur = 0;
        for (int lvl = 1; lvl < 8; lvl++) {
            int ne = s_neq[cur];
            int krem = selk - s_nwin;
            if (krem <= 0) break;
            if (ne == krem) {
                for (int i = tid; i < ne; i += 256) {
                    int q = atomicAdd(&s_nwin, 1);
                    wink[q] = keys[eqi[cur][i]];
                }
                if (tid == 0) s_neq[cur] = 0;
                __syncthreads();
                break;
            }
            int sh = 56 - 8 * lvl;
            h0[tid] = 0u;
            if (tid == 0) s_neq[cur ^ 1] = 0;
            __syncthreads();
            for (int i = tid; i < ne; i += 256) {
                unsigned int bin = (unsigned int)((keys[eqi[cur][i]] >> sh) & 0xFFull);
                unsigned int am = __activemask();
                unsigned int mk = __match_any_sync(am, bin);
                if (lane == __ffs(mk) - 1) atomicAdd(&h0[bin], __popc(mk));
            }
            __syncthreads();
            if (warp == 0) warp_cutoff(h0, krem, &s_b, lane);
            __syncthreads();
            int bsl = s_b;
            for (int i = tid; i < ne; i += 256) {
                unsigned short ix = eqi[cur][i];
                int byt = (int)((keys[ix] >> sh) & 0xFFull);
                if (byt > bsl) {
                    int q = atomicAdd(&s_nwin, 1);
                    wink[q] = keys[ix];
                } else if (byt == bsl) {
                    int q = atomicAdd(&s_neq[cur ^ 1], 1);
                    eqi[cur ^ 1][q] = ix;
                }
            }
            __syncthreads();
            cur ^= 1;
        }
        // ---- final flush (keys distinct -> remaining equals fill slots) ----
        {
            int krem = selk - s_nwin;
            if (krem > 0) {
                int ne = s_neq[cur];
                for (int i = tid; i < ne; i += 256) {
                    int q = atomicAdd(&s_nwin, 1);
                    if (q < selk) wink[q] = keys[eqi[cur][i]];
                }
            }
        }
    } else if (np > EQCAP) {
        // ---- fallback (adversarial cnt only): destructive argmax rounds ----
        for (int k = 0; k < selk; k++) {
            unsigned long long best = 0ull;
            for (int m = base + tid; m < end; m += 256) {
                unsigned long long key = mk_key(grow[m], m);
                if (key > best) best = key;
            }
            #pragma unroll
            for (int off = 16; off > 0; off >>= 1) {
                unsigned long long o = __shfl_down_sync(0xFFFFFFFFu, best, off);
                if (o > best) best = o;
            }
            if (lane == 0) red[warp] = best;
            __syncthreads();
            if (tid == 0) {
                unsigned long long bb = red[0];
                #pragma unroll
                for (int w = 1; w < 8; w++) if (red[w] > bb) bb = red[w];
                wink[k] = bb;
                int m = (int)(~(unsigned int)(bb & 0xFFFFFFFFull));
                grow[m] = -FLT_MAX;           // part range is block-private
            }
            __syncthreads();
        }
    }
    __syncthreads();

    // ---- write staging (pad with tiny distinct keys) ----
    if (tid < TOPK) {
        unsigned long long key = (tid < selk)
            ? wink[tid]
            : (unsigned long long)(p * TOPK + tid + 1);
        g_pk[b][p * TOPK + tid] = key;
    }
    __syncthreads();

    // ---- last part block for this query does the merge ----
    if (tid == 0) {
        __threadfence();
        s_last = (atomicAdd(&g_qdone[b], 1) == P_PARTS - 1) ? 1 : 0;
    }
    __syncthreads();
    if (!s_last) return;
    __threadfence();   // acquire: other parts' g_pk writes

    unsigned long long mine = g_pk[b][tid];
    __syncthreads();   // (keys array reuse barrier not needed; use registers)
    // broadcast all 256 keys through shared for the rank count
    keys[tid] = mine;
    __syncthreads();
    int rank = 0;
    #pragma unroll 8
    for (int j = 0; j < P_PARTS * TOPK; j++)
        rank += (keys[j] > mine) ? 1 : 0;
    if (rank < TOPK) {
        sv[rank] = u2f_ord((unsigned int)(mine >> 32));
        si[rank] = (int)(~(unsigned int)(mine & 0xFFFFFFFFull));
    }
    __syncthreads();

    // candidate position -> original row index
    if (tid < TOPK) si[tid] = g_cidx[si[tid]];
    __syncthreads();

    // softmax over the 32 selected logits (order-invariant)
    if (tid < 32) {
        float v = sv[tid];
        float mx = v;
        #pragma unroll
        for (int off = 16; off > 0; off >>= 1)
            mx = fmaxf(mx, __shfl_xor_sync(0xFFFFFFFFu, mx, off));
        float e = expf(v - mx);
        float ssum = e;
        #pragma unroll
        for (int off = 16; off > 0; off >>= 1)
            ssum += __shfl_xor_sync(0xFFFFFFFFu, ssum, off);
        sv[tid] = e / ssum;
    }
    __syncthreads();

    // gather: out[b, d] = sum_k attn[k] * V[idx_k, d]   (tid == d)
    float acc = 0.0f;
    #pragma unroll
    for (int k = 0; k < TOPK; k++)
        acc += sv[k] * Vbank[(size_t)si[k] * DIM + tid];
    out[b * DIM + tid] = acc;
}

// ---------------------------------------------------------------------------
extern "C" void kernel_launch(void* const* d_in, const int* in_sizes, int n_in,
                              void* d_out, int out_size) {
    const float* query = (const float*)d_in[0];
    const float* Kbank = (const float*)d_in[1];
    const float* Vbank = (const float*)d_in[2];
    const float* times = (const float*)d_in[3];
    const float* qtime = (const float*)d_in[4];
    float* out = (float*)d_out;

    int B = in_sizes[0] / DIM;
    int N = in_sizes[3];

    int logits_smem = (DIM * QG + DIM * CG) * (int)sizeof(float);  // 96 KB
    cudaFuncSetAttribute(k_logits, cudaFuncAttributeMaxDynamicSharedMemorySize,
                         logits_smem);

    k_pre<<<PRE_BLOCKS, 256>>>(times, qtime, query, N, B);
    dim3 g2(74, (B + QG - 1) / QG);       // 296 blocks = 2/SM
    k_logits<<<g2, 128, logits_smem>>>(Kbank, B);
    dim3 g3(P_PARTS, (unsigned)B);
    k_sel<<<g3, 256>>>(Vbank, out, B);
}

// round 8
// speedup vs baseline: 1.0326x; 1.0326x over previous
#include <cuda_runtime.h>
#include <float.h>
#include <math.h>

// Problem constants (shapes fixed by the dataset)
#define DIM       256
#define MAXB      128
#define TOPK      32
#define CAND_CAP  65536

#define INV_TAU   10.0f     // 1 / 0.1
#define PEN_COEF  0.25f     // BETA / (2*SIGMA^2) = 0.5 / 2
#define SIM_BOUND 10.0f     // max |q.K| / tau  (q, K unit-norm)

#define QG 32               // queries per logits block
#define CG 64               // candidates per logits chunk
#define PRE_BLOCKS 148      // <= SM count: all resident -> spin barrier is safe
#define P_PARTS 8           // selection parts per query
#define EQCAP 2048          // per-part element capacity (fast path)
#define RANKCAP 512         // rank-resolve shortcut limit

// ---------------- scratch (device globals; no allocation allowed) ----------
__device__ unsigned int g_ctr;                       // monotonic epoch counter
__device__ int          g_count;
__device__ int          g_qdone[MAXB];
__device__ float        g_minblk[PRE_BLOCKS][32];
__device__ int          g_cidx[CAND_CAP];
__device__ float        g_cpen[CAND_CAP];
__device__ float        g_qn[MAXB * DIM];
__device__ float        g_logits[(size_t)MAXB * CAND_CAP];           // 32 MB
__device__ unsigned long long g_pk[MAXB][P_PARTS * TOPK];            // staging

// order-preserving float <-> uint (descending float == descending uint)
__device__ __forceinline__ unsigned int f2u_ord(float f) {
    unsigned int u = __float_as_uint(f);
    return (u & 0x80000000u) ? ~u : (u | 0x80000000u);
}
__device__ __forceinline__ float u2f_ord(unsigned int u) {
    return (u & 0x80000000u) ? __uint_as_float(u & 0x7FFFFFFFu)
                             : __uint_as_float(~u);
}
// 64-bit selection key: value (ordered) high, ~index low. Distinct keys;
// bigger == better; lower index wins ties (== jax top_k order).
__device__ __forceinline__ unsigned long long mk_key(float v, int m) {
    return ((unsigned long long)f2u_ord(v) << 32) |
           (unsigned int)(~(unsigned int)m);
}

// ---------------------------------------------------------------------------
// Kernel 1 (fused): reset + query L2-norm + SAMPLED per-residue penalty
// minima + monotonic grid barrier + threshold + float4 candidate compaction.
// Grid = 148 x 1024 (1 block/SM, 32 warps -> real latency hiding).
//
// Threshold soundness: pass 1 samples rows 0..nb*1024-1, partitioned into 32
// disjoint residue groups by (n mod 32) (stride multiples of 32 keep each
// thread's residue fixed). The 32 per-group minima are attained at 32
// DISTINCT rows, so max(group minima) >= 32nd-smallest penalty overall.
// thresh = that bound + 2*SIM_BOUND + margin never drops a true top-32 row
// of any query, and guarantees cnt >= 32. Sampling only loosens the bound
// (<1% more candidates), never breaks it.
// ---------------------------------------------------------------------------
__global__ void __launch_bounds__(1024) k_pre(const float* __restrict__ times,
                                              const float* __restrict__ qtime,
                                              const float* __restrict__ query,
                                              int N, int B) {
    __shared__ float s[1024];
    __shared__ float sth;
    int tid = threadIdx.x, bid = blockIdx.x;
    int nb = gridDim.x;
    int lane = tid & 31, warp = tid >> 5;

    // --- per-launch resets (ordered before barrier by threadfence below) ---
    if (bid == 0) {
        if (tid == 0) g_count = 0;
        if (tid < MAXB) g_qdone[tid] = 0;
    }

    // --- query L2 normalization (matches F.normalize, eps=1e-12) ---
    float v = 0.0f;
    if (bid < B && tid < DIM) v = query[bid * DIM + tid];
    {
        float ss = v * v;
        #pragma unroll
        for (int off = 16; off > 0; off >>= 1)
            ss += __shfl_xor_sync(0xFFFFFFFFu, ss, off);
        if (lane == 0) s[warp] = ss;
        __syncthreads();
        if (tid == 0) {
            float t = 0.0f;
            #pragma unroll
            for (int w = 0; w < 8; w++) t += s[w];   // dims live in warps 0..7
            s[0] = fmaxf(sqrtf(t), 1e-12f);
        }
        __syncthreads();
        float nrm = s[0];
        if (bid < B && tid < DIM) g_qn[bid * DIM + tid] = v / nrm;
        __syncthreads();                              // s reused below
    }

    float qt = qtime[0];

    // --- pass 1 (sampled): ONE load per thread, per-residue minima ---
    {
        int n = bid * 1024 + tid;
        float p = FLT_MAX;
        if (n < N) { float dt = qt - times[n]; p = PEN_COEF * dt * dt; }
        s[tid] = p;
        __syncthreads();
        #pragma unroll
        for (int st = 512; st >= 32; st >>= 1) {      // offsets % 32 == 0
            if (tid < st) s[tid] = fminf(s[tid], s[tid + st]);
            __syncthreads();
        }
        if (tid < 32) g_minblk[bid][tid] = s[tid];
    }
    __threadfence();
    __syncthreads();

    // --- monotonic grid barrier (graph-replay safe: +nb tickets per launch) ---
    if (tid == 0) {
        unsigned int ticket = atomicAdd(&g_ctr, 1u);
        unsigned int target = (ticket / nb + 1u) * nb;
        while (atomicAdd(&g_ctr, 0u) < target) __nanosleep(32);
        __threadfence();
    }
    __syncthreads();

    // --- threshold: per-residue min over blocks, then max over residues ---
    {
        int r = tid & 31, sub = tid >> 5;             // 32 threads per residue
        float m = FLT_MAX;
        for (int i = sub; i < nb; i += 32) m = fminf(m, g_minblk[i][r]);
        s[tid] = m;
        __syncthreads();
        #pragma unroll
        for (int st = 512; st >= 32; st >>= 1) {
            if (tid < st) s[tid] = fminf(s[tid], s[tid + st]);
            __syncthreads();
        }
        if (tid == 0) {
            float mx = -FLT_MAX;
            #pragma unroll
            for (int g = 0; g < 32; g++) mx = fmaxf(mx, s[g]);
            sth = mx + 2.0f * SIM_BOUND + 4.0f;       // sound bound + fp margin
        }
        __syncthreads();
    }
    float thresh = sth;

    // --- pass 2 (full): float4 loads + compaction ---
    const float4* t4 = (const float4*)times;
    int n4 = N >> 2;
    for (int vv = bid * 1024 + tid; vv < n4; vv += nb * 1024) {
        float4 tv = t4[vv];
        float d0 = qt - tv.x, d1 = qt - tv.y, d2 = qt - tv.z, d3 = qt - tv.w;
        float pv[4] = {PEN_COEF * d0 * d0, PEN_COEF * d1 * d1,
                       PEN_COEF * d2 * d2, PEN_COEF * d3 * d3};
        int cc[4];
        int loc = 0;
        #pragma unroll
        for (int j = 0; j < 4; j++) { cc[j] = pv[j] <= thresh; loc += cc[j]; }
        if (loc) {
            int pos = atomicAdd(&g_count, loc);
            int nbase = vv * 4;
            #pragma unroll
            for (int j = 0; j < 4; j++) {
                if (cc[j]) {
                    if (pos < CAND_CAP) { g_cidx[pos] = nbase + j; g_cpen[pos] = pv[j]; }
                    pos++;
                }
            }
        }
    }
    {   // scalar tail (N % 4)
        int rem = N - n4 * 4;
        if (bid == 0 && tid < rem) {
            int n = n4 * 4 + tid;
            float dt = qt - times[n];
            float p = PEN_COEF * dt * dt;
            if (p <= thresh) {
                int pos = atomicAdd(&g_count, 1);
                if (pos < CAND_CAP) { g_cidx[pos] = n; g_cpen[pos] = p; }
            }
        }
    }
}

// ---------------------------------------------------------------------------
// Kernel 2: exact fp32 logits, register-tiled (proven version).
// Block tile QG=32 x CG=64, 128 threads, 4x4 register tile, 96 KB SMEM,
// 2 blocks/SM. Inner d-step: 2x LDS.128 + 16 FMA.
// ---------------------------------------------------------------------------
extern __shared__ float s_dyn[];   // qs[DIM*QG] then kv[DIM*CG]

__global__ void __launch_bounds__(128, 2)
k_logits(const float* __restrict__ Kbank, int B) {
    float* qs = s_dyn;             // [d*QG + q]
    float* kv = s_dyn + DIM * QG;  // [d*CG + c]
    __shared__ float spen[CG];

    int tid = threadIdx.x;
    int grp = blockIdx.y;
    int cnt = min(g_count, CAND_CAP);
    if (cnt <= 0) return;

    const float4* qn4 = (const float4*)g_qn;
    const float4* K4  = (const float4*)Kbank;

    // ---- load 32 queries transposed ----
    {
        int q = tid & 31, d4b = tid >> 5;
        int b = grp * QG + q;
        #pragma unroll
        for (int i = 0; i < 16; i++) {
            int d4 = d4b + 4 * i;
            float4 v = (b < B) ? qn4[(size_t)b * (DIM / 4) + d4]
                               : make_float4(0.f, 0.f, 0.f, 0.f);
            qs[(d4 * 4 + 0) * QG + q] = v.x;
            qs[(d4 * 4 + 1) * QG + q] = v.y;
            qs[(d4 * 4 + 2) * QG + q] = v.z;
            qs[(d4 * 4 + 3) * QG + q] = v.w;
        }
    }

    int cq = tid & 15, qq = tid >> 4;
    int c0 = cq * 4, q0 = qq * 4;

    for (int m0 = blockIdx.x * CG; m0 < cnt; m0 += gridDim.x * CG) {
        __syncthreads();

        // ---- load 64 candidate K rows transposed ----
        {
            int c = tid & 63, d4b = tid >> 6;
            int row = g_cidx[min(m0 + c, cnt - 1)];
            #pragma unroll
            for (int i = 0; i < 32; i++) {
                int d4 = d4b + 2 * i;
                float4 v = K4[(size_t)row * (DIM / 4) + d4];
                kv[(d4 * 4 + 0) * CG + c] = v.x;
                kv[(d4 * 4 + 1) * CG + c] = v.y;
                kv[(d4 * 4 + 2) * CG + c] = v.z;
                kv[(d4 * 4 + 3) * CG + c] = v.w;
            }
        }
        if (tid < CG) spen[tid] = g_cpen[min(m0 + tid, cnt - 1)];
        __syncthreads();

        float acc[16];
        #pragma unroll
        for (int i = 0; i < 16; i++) acc[i] = 0.0f;

        #pragma unroll 4
        for (int d = 0; d < DIM; d++) {
            float4 kf = *(const float4*)&kv[d * CG + c0];
            float4 qf = *(const float4*)&qs[d * QG + q0];
            acc[0]  += qf.x * kf.x;  acc[1]  += qf.x * kf.y;
            acc[2]  += qf.x * kf.z;  acc[3]  += qf.x * kf.w;
            acc[4]  += qf.y * kf.x;  acc[5]  += qf.y * kf.y;
            acc[6]  += qf.y * kf.z;  acc[7]  += qf.y * kf.w;
            acc[8]  += qf.z * kf.x;  acc[9]  += qf.z * kf.y;
            acc[10] += qf.z * kf.z;  acc[11] += qf.z * kf.w;
            acc[12] += qf.w * kf.x;  acc[13] += qf.w * kf.y;
            acc[14] += qf.w * kf.z;  acc[15] += qf.w * kf.w;
        }

        float p0 = spen[c0 + 0], p1 = spen[c0 + 1];
        float p2 = spen[c0 + 2], p3 = spen[c0 + 3];
        bool full = (m0 + c0 + 3) < cnt;
        #pragma unroll
        for (int qj = 0; qj < 4; qj++) {
            int b = grp * QG + q0 + qj;
            if (b >= B) break;
            float* dst = g_logits + (size_t)b * CAND_CAP + m0 + c0;
            float4 v;
            v.x = acc[qj * 4 + 0] * INV_TAU - p0;
            v.y = acc[qj * 4 + 1] * INV_TAU - p1;
            v.z = acc[qj * 4 + 2] * INV_TAU - p2;
            v.w = acc[qj * 4 + 3] * INV_TAU - p3;
            if (full) {
                *(float4*)dst = v;
            } else {
                float vv[4] = {v.x, v.y, v.z, v.w};
                for (int cj = 0; cj < 4; cj++)
                    if (m0 + c0 + cj < cnt) dst[cj] = vv[cj];
            }
        }
    }
}

// ---------------------------------------------------------------------------
// Warp-0 register suffix-scan over a 256-bin histogram; returns the unique
// bin t with sfx[t] >= K and sfx[t+1] < K via *out. 8 bins/lane + 5 shfls.
// ---------------------------------------------------------------------------
__device__ __forceinline__ void warp_cutoff(const unsigned int* h, int K,
                                            int* out, int lane) {
    unsigned int loc[8];
    int b8 = lane * 8;
    #pragma unroll
    for (int k = 0; k < 8; k++) loc[k] = h[b8 + k];
    #pragma unroll
    for (int k = 6; k >= 0; k--) loc[k] += loc[k + 1];      // local suffix
    unsigned int total = loc[0];
    unsigned int val = total;
    #pragma unroll
    for (int off = 1; off < 32; off <<= 1) {
        unsigned int o = __shfl_down_sync(0xFFFFFFFFu, val, off);
        if (lane + off < 32) val += o;
    }
    unsigned int excl = val - total;                        // suffix of lanes > lane
    #pragma unroll
    for (int k = 0; k < 8; k++) {
        unsigned int sfx = loc[k] + excl;
        unsigned int abv = (k < 7) ? (loc[k + 1] + excl) : excl;
        if (sfx >= (unsigned)K && abv < (unsigned)K) *out = b8 + k;
    }
}

// ---------------------------------------------------------------------------
// Kernel 3: per (query, part) EXACT top-32 via radix level 0 + rank-resolve
// (keys distinct -> exactly krem winners with rank < krem among equals), with
// deeper radix only if the equal-prefix list exceeds RANKCAP. The LAST part
// block per query merges all 256 staged keys by rank, softmaxes, gathers V.
// Grid (P_PARTS, B), 256 threads.
// ---------------------------------------------------------------------------
__global__ void __launch_bounds__(256) k_sel(const float* __restrict__ Vbank,
                                             float* __restrict__ out, int B) {
    __shared__ unsigned long long keys[EQCAP];
    __shared__ unsigned short eqi[2][EQCAP];
    __shared__ unsigned int h0[256];
    __shared__ unsigned long long wink[TOPK];
    __shared__ unsigned long long red[8];
    __shared__ int s_nwin, s_neq[2], s_b, s_last;
    __shared__ float sv[TOPK];
    __shared__ int   si[TOPK];

    int p = blockIdx.x, b = blockIdx.y;
    int tid = threadIdx.x, lane = tid & 31, warp = tid >> 5;
    int cnt = min(g_count, CAND_CAP);
    float* grow = g_logits + (size_t)b * CAND_CAP;

    int base = (int)(((long long)cnt * p) / P_PARTS);
    int end  = (int)(((long long)cnt * (p + 1)) / P_PARTS);
    int np = end - base;
    int selk = min(TOPK, np);

    if (tid == 0) { s_nwin = 0; s_neq[0] = 0; s_neq[1] = 0; }
    h0[tid] = 0u;
    __syncthreads();

    if (np > 0 && np <= EQCAP) {
        // ---- single gmem pass: stage keys in SMEM + histogram byte 7 ----
        for (int i = tid; i < np; i += 256) {
            unsigned long long key = mk_key(grow[base + i], base + i);
            keys[i] = key;
            unsigned int bin = (unsigned int)(key >> 56);
            unsigned int am = __activemask();
            unsigned int mk = __match_any_sync(am, bin);
            if (lane == __ffs(mk) - 1) atomicAdd(&h0[bin], __popc(mk));
        }
        __syncthreads();
        if (warp == 0) warp_cutoff(h0, selk, &s_b, lane);
        __syncthreads();
        int bs = s_b;
        for (int i = tid; i < np; i += 256) {
            int byt = (int)(keys[i] >> 56);
            if (byt > bs) {
                int q = atomicAdd(&s_nwin, 1);
                wink[q] = keys[i];
            } else if (byt == bs) {
                int q = atomicAdd(&s_neq[0], 1);
                eqi[0][q] = (unsigned short)i;
            }
        }
        __syncthreads();

        // ---- resolve equals: rank shortcut, deeper radix only if large ----
        int cur = 0;
        for (int lvl = 1; lvl < 8; lvl++) {
            int ne = s_neq[cur];
            int krem = selk - s_nwin;
            if (krem <= 0) break;
            if (ne == krem) {
                for (int i = tid; i < ne; i += 256) {
                    int q = atomicAdd(&s_nwin, 1);
                    wink[q] = keys[eqi[cur][i]];
                }
                break;
            }
            if (ne <= RANKCAP) {
                // exact rank among equals (uniform j -> LDS broadcasts)
                for (int i = tid; i < ne; i += 256) {
                    unsigned long long key = keys[eqi[cur][i]];
                    int rank = 0;
                    for (int j = 0; j < ne; j++)
                        rank += (keys[eqi[cur][j]] > key) ? 1 : 0;
                    if (rank < krem) {
                        int q = atomicAdd(&s_nwin, 1);
                        wink[q] = key;
                    }
                }
                break;
            }
            // deeper radix level
            int sh = 56 - 8 * lvl;
            h0[tid] = 0u;
            if (tid == 0) s_neq[cur ^ 1] = 0;
            __syncthreads();
            for (int i = tid; i < ne; i += 256) {
                unsigned int bin = (unsigned int)((keys[eqi[cur][i]] >> sh) & 0xFFull);
                unsigned int am = __activemask();
                unsigned int mk = __match_any_sync(am, bin);
                if (lane == __ffs(mk) - 1) atomicAdd(&h0[bin], __popc(mk));
            }
            __syncthreads();
            if (warp == 0) warp_cutoff(h0, krem, &s_b, lane);
            __syncthreads();
            int bsl = s_b;
            for (int i = tid; i < ne; i += 256) {
                unsigned short ix = eqi[cur][i];
                int byt = (int)((keys[ix] >> sh) & 0xFFull);
                if (byt > bsl) {
                    int q = atomicAdd(&s_nwin, 1);
                    wink[q] = keys[ix];
                } else if (byt == bsl) {
                    int q = atomicAdd(&s_neq[cur ^ 1], 1);
                    eqi[cur ^ 1][q] = ix;
                }
            }
            __syncthreads();
            cur ^= 1;
        }
    } else if (np > EQCAP) {
        // ---- fallback (adversarial cnt only): destructive argmax rounds ----
        for (int k = 0; k < selk; k++) {
            unsigned long long best = 0ull;
            for (int m = base + tid; m < end; m += 256) {
                unsigned long long key = mk_key(grow[m], m);
                if (key > best) best = key;
            }
            #pragma unroll
            for (int off = 16; off > 0; off >>= 1) {
                unsigned long long o = __shfl_down_sync(0xFFFFFFFFu, best, off);
                if (o > best) best = o;
            }
            if (lane == 0) red[warp] = best;
            __syncthreads();
            if (tid == 0) {
                unsigned long long bb = red[0];
                #pragma unroll
                for (int w = 1; w < 8; w++) if (red[w] > bb) bb = red[w];
                wink[k] = bb;
                int m = (int)(~(unsigned int)(bb & 0xFFFFFFFFull));
                grow[m] = -FLT_MAX;           // part range is block-private
            }
            __syncthreads();
        }
    }
    __syncthreads();

    // ---- write staging (pad with tiny distinct keys; real keys >= 2^32) ----
    if (tid < TOPK) {
        unsigned long long key = (tid < selk)
            ? wink[tid]
            : (unsigned long long)(p * TOPK + tid + 1);
        g_pk[b][p * TOPK + tid] = key;
    }
    __syncthreads();

    // ---- last part block for this query does the merge ----
    if (tid == 0) {
        __threadfence();
        s_last = (atomicAdd(&g_qdone[b], 1) == P_PARTS - 1) ? 1 : 0;
    }
    __syncthreads();
    if (!s_last) return;
    __threadfence();   // acquire: other parts' g_pk writes

    unsigned long long mine = g_pk[b][tid];
    keys[tid] = mine;
    __syncthreads();
    int rank = 0;
    #pragma unroll 8
    for (int j = 0; j < P_PARTS * TOPK; j++)
        rank += (keys[j] > mine) ? 1 : 0;
    if (rank < TOPK) {
        sv[rank] = u2f_ord((unsigned int)(mine >> 32));
        si[rank] = (int)(~(unsigned int)(mine & 0xFFFFFFFFull));
    }
    __syncthreads();

    // candidate position -> original row index
    if (tid < TOPK) si[tid] = g_cidx[si[tid]];
    __syncthreads();

    // softmax over the 32 selected logits (order-invariant)
    if (tid < 32) {
        float v = sv[tid];
        float mx = v;
        #pragma unroll
        for (int off = 16; off > 0; off >>= 1)
            mx = fmaxf(mx, __shfl_xor_sync(0xFFFFFFFFu, mx, off));
        float e = expf(v - mx);
        float ssum = e;
        #pragma unroll
        for (int off = 16; off > 0; off >>= 1)
            ssum += __shfl_xor_sync(0xFFFFFFFFu, ssum, off);
        sv[tid] = e / ssum;
    }
    __syncthreads();

    // gather: out[b, d] = sum_k attn[k] * V[idx_k, d]   (tid == d)
    float acc = 0.0f;
    #pragma unroll
    for (int k = 0; k < TOPK; k++)
        acc += sv[k] * Vbank[(size_t)si[k] * DIM + tid];
    out[b * DIM + tid] = acc;
}

// ---------------------------------------------------------------------------
extern "C" void kernel_launch(void* const* d_in, const int* in_sizes, int n_in,
                              void* d_out, int out_size) {
    const float* query = (const float*)d_in[0];
    const float* Kbank = (const float*)d_in[1];
    const float* Vbank = (const float*)d_in[2];
    const float* times = (const float*)d_in[3];
    const float* qtime = (const float*)d_in[4];
    float* out = (float*)d_out;

    int B = in_sizes[0] / DIM;
    int N = in_sizes[3];

    int logits_smem = (DIM * QG + DIM * CG) * (int)sizeof(float);  // 96 KB
    cudaFuncSetAttribute(k_logits, cudaFuncAttributeMaxDynamicSharedMemorySize,
                         logits_smem);

    k_pre<<<PRE_BLOCKS, 1024>>>(times, qtime, query, N, B);
    dim3 g2(74, (B + QG - 1) / QG);       // 296 blocks = 2/SM
    k_logits<<<g2, 128, logits_smem>>>(Kbank, B);
    dim3 g3(P_PARTS, (unsigned)B);
    k_sel<<<g3, 256>>>(Vbank, out, B);
}